// round 10
// baseline (speedup 1.0000x reference)
#include <cuda_runtime.h>
#include <cuda_fp16.h>
#include <cstdint>

#define D_IN   128
#define NBASES 4
#define NCOLS  512
#define N_MAX  100096          // multiple of 256
#define NBLK   (N_MAX / 256)   // 391
#define E_MAX  655360
#define K1_RBLKS 296
#define PERM_BLKS 148
#define DONE_IDX (N_MAX + NBLK)
#define GEMM_TILES (N_MAX / 128)   // 782

// ---------------- scratch ----------------
__device__ __align__(16) __half g_Xh[(size_t)N_MAX * D_IN];       // fp16 X
__device__ __align__(16) unsigned char g_Bt2[NBASES * 32768];     // swizzled [512 n][256B]
__device__ int    g_hist[N_MAX + NBLK + 1];   // hist | scan aggregates | perm-done flag
__device__ int    g_rowptr[N_MAX + 1];
__device__ int    g_cursor[N_MAX];
__device__ int    g_dst_s[E_MAX];
__device__ float4 g_c_s[E_MAX];

// ---------------- helpers ----------------
static __device__ __forceinline__ uint32_t smem_u32(const void* p) {
    uint32_t a;
    asm("{ .reg .u64 t; cvta.to.shared.u64 t, %1; cvt.u32.u64 %0, t; }" : "=r"(a) : "l"(p));
    return a;
}
#define LDSM4(r, addr) \
    asm volatile("ldmatrix.sync.aligned.m8n8.x4.shared.b16 {%0,%1,%2,%3}, [%4];" \
        : "=r"((r)[0]), "=r"((r)[1]), "=r"((r)[2]), "=r"((r)[3]) : "r"(addr))
#define MMA_F16(c, a, b0, b1) \
    asm volatile("mma.sync.aligned.m16n8k16.row.col.f32.f16.f16.f32 " \
        "{%0,%1,%2,%3}, {%4,%5,%6,%7}, {%8,%9}, {%0,%1,%2,%3};" \
        : "+f"((c)[0]), "+f"((c)[1]), "+f"((c)[2]), "+f"((c)[3]) \
        : "r"((a)[0]), "r"((a)[1]), "r"((a)[2]), "r"((a)[3]), "r"(b0), "r"(b1))

static __device__ __forceinline__ uint32_t packh(__half a, __half b) {
    return ((uint32_t)__half_as_ushort(b) << 16) | (uint32_t)__half_as_ushort(a);
}

// ================= K1: zero-out | convert_x | hist | prep_b2 =================
__global__ void __launch_bounds__(256)
k1_kernel(const float* __restrict__ X,
          const float* __restrict__ w_bases,
          const int*   __restrict__ esrc,
          float4*      __restrict__ out,
          int total4, int out4, int E)
{
    const int region = blockIdx.x / K1_RBLKS;          // 0..3
    const int tid0 = (blockIdx.x % K1_RBLKS) * 256 + threadIdx.x;
    const int stride = K1_RBLKS * 256;

    if (region == 0) {
        const float4 z = make_float4(0.f, 0.f, 0.f, 0.f);
        for (int i = tid0; i < out4; i += stride) out[i] = z;
    } else if (region == 1) {
        for (int i = tid0; i < total4; i += stride) {
            float4 v = reinterpret_cast<const float4*>(X)[i];
            reinterpret_cast<uint2*>(g_Xh)[i] =
                make_uint2(packh(__float2half_rn(v.x), __float2half_rn(v.y)),
                           packh(__float2half_rn(v.z), __float2half_rn(v.w)));
        }
    } else if (region == 2) {
        for (int e = tid0; e < E; e += stride) atomicAdd(&g_hist[esrc[e]], 1);
    } else {
        // w_bases[b][k][o] -> swizzled B image: row n = b*128+o, 256B rows
        for (int id = tid0; id < NBASES * 128 * 128; id += stride) {
            const int b = id >> 14, k = (id >> 7) & 127, o = id & 127;
            const int nrow = b * 128 + o;
            uint32_t off = (uint32_t)nrow * 256 + k * 2;
            off ^= ((off >> 4) & 0x70);
            *reinterpret_cast<__half*>(g_Bt2 + off) = __float2half_rn(w_bases[id]);
        }
    }
}

// ================= K_scan: single-pass scan with aggregate lookback =========
__global__ void __launch_bounds__(256)
scan_kernel(int E)
{
    __shared__ int s_w[8];
    __shared__ int s_off;
    const int t = threadIdx.x, w = t >> 5, lane = t & 31;
    const int blk = blockIdx.x;
    const int i = blk * 256 + t;

    const int x = g_hist[i];
    int v = x;
    #pragma unroll
    for (int o = 1; o < 32; o <<= 1) {
        int y = __shfl_up_sync(0xFFFFFFFF, v, o);
        if (lane >= o) v += y;
    }
    if (lane == 31) s_w[w] = v;
    __syncthreads();
    if (t < 8) {
        int sv = s_w[t];
        #pragma unroll
        for (int o = 1; o < 8; o <<= 1) {
            int y = __shfl_up_sync(0xFF, sv, o);
            if (t >= o) sv += y;
        }
        s_w[t] = sv;
    }
    __syncthreads();
    const int local_excl = ((w > 0) ? s_w[w - 1] : 0) + v - x;

    if (t == 0) {
        int total = s_w[7];
        asm volatile("st.global.release.gpu.b32 [%0], %1;"
                     :: "l"(&g_hist[N_MAX + blk]), "r"(total + 1) : "memory");
    }
    if (w == 0) {
        int sum = 0;
        for (int j0 = 0; j0 < blk; j0 += 32) {
            const int j = j0 + lane;
            int a = 0;
            if (j < blk) {
                do {
                    asm volatile("ld.global.acquire.gpu.b32 %0, [%1];"
                                 : "=r"(a) : "l"(&g_hist[N_MAX + j]) : "memory");
                } while (a == 0);
                a -= 1;
            }
            #pragma unroll
            for (int o = 16; o > 0; o >>= 1) a += __shfl_down_sync(0xFFFFFFFF, a, o);
            if (lane == 0) sum += a;
        }
        if (lane == 0) s_off = sum;
    }
    __syncthreads();

    const int r = s_off + local_excl;
    g_rowptr[i] = r;
    g_cursor[i] = r;
    if (i == N_MAX - 1) g_rowptr[N_MAX] = E;
}

// ======== K2: perm (bids 0..147) | GEMM+scatter fused (bids 148..929) =======
#define SM_A   0
#define SM_B   32768
#define SM_XW  65536
#define XW_STRIDE 1040          // 1024 + 16B pad (bank rotation)
#define SM_TOTAL (65536 + 128 * XW_STRIDE)   // 198656

__global__ void __launch_bounds__(256, 1)
k2_kernel(const int* __restrict__ esrc, const int* __restrict__ edst,
          const int* __restrict__ erel, const float* __restrict__ eval,
          const float* __restrict__ w_rel, float* __restrict__ out, int E)
{
    const int tid = threadIdx.x;

    if (blockIdx.x < PERM_BLKS) {
        // ---- perm: scatter edges into src-sorted order, coeffs precombined
        for (int e = blockIdx.x * 256 + tid; e < E; e += PERM_BLKS * 256) {
            const int s = esrc[e];
            const int pos = atomicAdd(&g_cursor[s], 1);
            g_dst_s[pos] = edst[e];
            const int r = erel[e];
            const float v = eval[e];
            float4 c;
            c.x = v * __ldg(w_rel + r * NBASES + 0);
            c.y = v * __ldg(w_rel + r * NBASES + 1);
            c.z = v * __ldg(w_rel + r * NBASES + 2);
            c.w = v * __ldg(w_rel + r * NBASES + 3);
            g_c_s[pos] = c;
        }
        __threadfence();
        __syncthreads();
        if (tid == 0) atomicAdd(&g_hist[DONE_IDX], 1);
        return;
    }

    // ---------------- GEMM (all 4 bases) + scatter from smem ----------------
    extern __shared__ char smem[];
    const uint32_t sb = smem_u32(smem);
    const int m0 = (blockIdx.x - PERM_BLKS) * 128;
    const int wid = tid >> 5, lane = tid & 31;

    // A tile: 128 rows x 256B, XOR-swizzled (bits[8:10] -> [4:6])
    for (int i = tid; i < 2048; i += 256) {
        const int row = i >> 4, seg = (i & 15) << 4;
        uint4 v = *reinterpret_cast<const uint4*>(
            reinterpret_cast<const char*>(g_Xh) + (size_t)(m0 + row) * 256 + seg);
        *reinterpret_cast<uint4*>(smem + SM_A + row * 256 + (seg ^ ((row & 7) << 4))) = v;
    }
    // B base 0: linear copy of pre-swizzled image chunk
    for (int i = tid; i < 2048; i += 256)
        reinterpret_cast<uint4*>(smem + SM_B)[i] =
            reinterpret_cast<const uint4*>(g_Bt2)[i];
    __syncthreads();

    const int warp_m = (wid & 3) * 32;
    const int warp_n = (wid >> 2) * 64;

    const int a_row = warp_m + (lane & 15);
    const uint32_t a_base = sb + SM_A + a_row * 256;
    const uint32_t a_xor  = (uint32_t)((a_row & 7) << 4);
    const uint32_t a_col0 = (uint32_t)((lane >> 4) * 16);
    const int b_row = warp_n + ((lane >> 4) << 3) + (lane & 7);
    const uint32_t b_base = sb + SM_B + b_row * 256;
    const uint32_t b_xor  = (uint32_t)((b_row & 7) << 4);
    const uint32_t b_col0 = (uint32_t)(((lane >> 3) & 1) * 16);

    #pragma unroll 1
    for (int b = 0; b < NBASES; ++b) {
        float acc[2][8][4];
        #pragma unroll
        for (int mt = 0; mt < 2; ++mt)
            #pragma unroll
            for (int nt = 0; nt < 8; ++nt)
                #pragma unroll
                for (int i = 0; i < 4; ++i) acc[mt][nt][i] = 0.f;

        #pragma unroll
        for (int ks = 0; ks < 8; ++ks) {
            const uint32_t kb = (uint32_t)ks * 32;
            uint32_t ah[2][4];
            LDSM4(ah[0], a_base + ((a_col0 + kb) ^ a_xor));
            LDSM4(ah[1], a_base + 16 * 256 + ((a_col0 + kb) ^ a_xor));
            #pragma unroll
            for (int j = 0; j < 4; ++j) {
                uint32_t bf[4];
                LDSM4(bf, b_base + j * 16 * 256 + ((b_col0 + kb) ^ b_xor));
                #pragma unroll
                for (int mt = 0; mt < 2; ++mt) {
                    MMA_F16(acc[mt][2 * j + 0], ah[mt], bf[0], bf[1]);
                    MMA_F16(acc[mt][2 * j + 1], ah[mt], bf[2], bf[3]);
                }
            }
        }

        // epilogue: fp16 into smem XW tile [row][512], stride 1040B
        const int r0w = warp_m + (lane >> 2);
        #pragma unroll
        for (int mt = 0; mt < 2; ++mt) {
            const int row = r0w + mt * 16;
            #pragma unroll
            for (int nt = 0; nt < 8; ++nt) {
                const int col = b * 128 + warp_n + nt * 8 + (lane & 3) * 2;
                *reinterpret_cast<__half2*>(smem + SM_XW + row * XW_STRIDE + col * 2) =
                    __floats2half2_rn(acc[mt][nt][0], acc[mt][nt][1]);
                *reinterpret_cast<__half2*>(smem + SM_XW + (row + 8) * XW_STRIDE + col * 2) =
                    __floats2half2_rn(acc[mt][nt][2], acc[mt][nt][3]);
            }
        }
        __syncthreads();     // all reads of B done, B buffer free
        if (b < NBASES - 1) {
            for (int i = tid; i < 2048; i += 256)
                reinterpret_cast<uint4*>(smem + SM_B)[i] =
                    reinterpret_cast<const uint4*>(g_Bt2 + (b + 1) * 32768)[i];
            __syncthreads();
        }
    }

    // ---- wait for perm completion (perm blocks are bids 0..147, no deps) ----
    if (tid == 0) {
        int dcnt;
        do {
            asm volatile("ld.global.acquire.gpu.b32 %0, [%1];"
                         : "=r"(dcnt) : "l"(&g_hist[DONE_IDX]) : "memory");
            if (dcnt >= PERM_BLKS) break;
            __nanosleep(200);
        } while (true);
    }
    __syncthreads();

    // ---- scatter own 128 srcs from smem XW tile ----
    for (int s = wid * 16; s < wid * 16 + 16; ++s) {
        const int src = m0 + s;
        const int beg = __ldg(g_rowptr + src);
        const int end = __ldg(g_rowptr + src + 1);
        if (beg >= end) continue;

        const char* rowp = smem + SM_XW + s * XW_STRIDE + lane * 8;
        float a[NBASES][4];
        #pragma unroll
        for (int b = 0; b < NBASES; ++b) {
            const uint2 v = *reinterpret_cast<const uint2*>(rowp + b * 256);
            const float2 lo = __half22float2(*reinterpret_cast<const __half2*>(&v.x));
            const float2 hi = __half22float2(*reinterpret_cast<const __half2*>(&v.y));
            a[b][0] = lo.x; a[b][1] = lo.y; a[b][2] = hi.x; a[b][3] = hi.y;
        }
        for (int j = beg; j < end; ++j) {
            const float4 c = __ldg(g_c_s + j);
            const int d = __ldg(g_dst_s + j);
            float4 acc;
            acc.x = fmaf(c.x, a[0][0], fmaf(c.y, a[1][0], fmaf(c.z, a[2][0], c.w * a[3][0])));
            acc.y = fmaf(c.x, a[0][1], fmaf(c.y, a[1][1], fmaf(c.z, a[2][1], c.w * a[3][1])));
            acc.z = fmaf(c.x, a[0][2], fmaf(c.y, a[1][2], fmaf(c.z, a[2][2], c.w * a[3][2])));
            acc.w = fmaf(c.x, a[0][3], fmaf(c.y, a[1][3], fmaf(c.z, a[2][3], c.w * a[3][3])));
            float* q = out + (size_t)d * 128 + lane * 4;
            asm volatile("red.global.add.v4.f32 [%0], {%1, %2, %3, %4};"
                         :: "l"(q), "f"(acc.x), "f"(acc.y), "f"(acc.z), "f"(acc.w)
                         : "memory");
        }
    }
}

// ================= launch =================
extern "C" void kernel_launch(void* const* d_in, const int* in_sizes, int n_in,
                              void* d_out, int out_size)
{
    const float* X       = (const float*)d_in[0];
    const int*   esrc    = (const int*)  d_in[1];
    const int*   edst    = (const int*)  d_in[2];
    const int*   erel    = (const int*)  d_in[3];
    const float* eval    = (const float*)d_in[4];
    const float* w_bases = (const float*)d_in[5];
    const float* w_rel   = (const float*)d_in[6];
    float*       out     = (float*)d_out;

    const int n = in_sizes[0] / D_IN;   // 100000
    const int E = in_sizes[1];          // 640000

    cudaFuncSetAttribute(k2_kernel, cudaFuncAttributeMaxDynamicSharedMemorySize, SM_TOTAL);

    // zero hist + scan aggregates + perm-done flag in one memset
    void* hist_ptr = nullptr;
    cudaGetSymbolAddress(&hist_ptr, g_hist);
    cudaMemsetAsync(hist_ptr, 0, (size_t)(N_MAX + NBLK + 1) * sizeof(int));

    const int total4 = n * D_IN / 4;
    const int out4 = out_size / 4;
    k1_kernel<<<4 * K1_RBLKS, 256>>>(X, w_bases, esrc, (float4*)d_out, total4, out4, E);
    scan_kernel<<<NBLK, 256>>>(E);
    k2_kernel<<<PERM_BLKS + GEMM_TILES, 256, SM_TOTAL>>>(esrc, edst, erel, eval, w_rel, out, E);
}

// round 12
// speedup vs baseline: 1.0285x; 1.0285x over previous
#include <cuda_runtime.h>
#include <cuda_fp16.h>
#include <cstdint>

#define D_IN   128
#define D_OUT  128
#define NBASES 4
#define NCOLS  512
#define N_MAX  100096          // multiple of 256
#define NBLK   (N_MAX / 256)   // 391
#define E_MAX  655360
#define K1_RBLKS 296

// ---------------- scratch ----------------
__device__ __align__(16) __half g_XWh[(size_t)N_MAX * NCOLS];  // [node][512] fp16
__device__ __align__(16) __half g_Xh[(size_t)N_MAX * D_IN];    // fp16 X
#define BT_STRIDE 136
__device__ __align__(16) __half g_Bt[NBASES][128 * BT_STRIDE];
// hist[N_MAX] | scan aggregates[NBLK]  (zeroed by one memset)
__device__ int    g_hist[N_MAX + NBLK];
__device__ int    g_rowptr[N_MAX + 1];
__device__ int    g_cursor[N_MAX];
__device__ int    g_dst_s[E_MAX];
__device__ float4 g_c_s[E_MAX];

// ---------------- helpers ----------------
static __device__ __forceinline__ uint32_t smem_u32(const void* p) {
    uint32_t a;
    asm("{ .reg .u64 t; cvta.to.shared.u64 t, %1; cvt.u32.u64 %0, t; }" : "=r"(a) : "l"(p));
    return a;
}
#define LDSM4(r, addr) \
    asm volatile("ldmatrix.sync.aligned.m8n8.x4.shared.b16 {%0,%1,%2,%3}, [%4];" \
        : "=r"((r)[0]), "=r"((r)[1]), "=r"((r)[2]), "=r"((r)[3]) : "r"(addr))
#define MMA_F16(c, a, b0, b1) \
    asm volatile("mma.sync.aligned.m16n8k16.row.col.f32.f16.f16.f32 " \
        "{%0,%1,%2,%3}, {%4,%5,%6,%7}, {%8,%9}, {%0,%1,%2,%3};" \
        : "+f"((c)[0]), "+f"((c)[1]), "+f"((c)[2]), "+f"((c)[3]) \
        : "r"((a)[0]), "r"((a)[1]), "r"((a)[2]), "r"((a)[3]), "r"(b0), "r"(b1))

static __device__ __forceinline__ uint32_t packh(__half a, __half b) {
    return ((uint32_t)__half_as_ushort(b) << 16) | (uint32_t)__half_as_ushort(a);
}

// ================= K1: zero-out | convert_x | hist | prep_b =================
__global__ void __launch_bounds__(256)
k1_kernel(const float* __restrict__ X,
          const float* __restrict__ w_bases,
          const int*   __restrict__ esrc,
          float4*      __restrict__ out,
          int total4, int out4, int E)
{
    const int region = blockIdx.x / K1_RBLKS;          // 0..3
    const int tid0 = (blockIdx.x % K1_RBLKS) * 256 + threadIdx.x;
    const int stride = K1_RBLKS * 256;

    if (region == 0) {
        const float4 z = make_float4(0.f, 0.f, 0.f, 0.f);
        for (int i = tid0; i < out4; i += stride) out[i] = z;
    } else if (region == 1) {
        for (int i = tid0; i < total4; i += stride) {
            float4 v = reinterpret_cast<const float4*>(X)[i];
            reinterpret_cast<uint2*>(g_Xh)[i] =
                make_uint2(packh(__float2half_rn(v.x), __float2half_rn(v.y)),
                           packh(__float2half_rn(v.z), __float2half_rn(v.w)));
        }
    } else if (region == 2) {
        for (int e = tid0; e < E; e += stride) atomicAdd(&g_hist[esrc[e]], 1);
    } else {
        for (int id = tid0; id < NBASES * D_IN * D_OUT; id += stride) {
            const int nn = id & 127, k = (id >> 7) & 127, b = id >> 14;
            g_Bt[b][nn * BT_STRIDE + k] = __float2half_rn(w_bases[id]);
        }
    }
}

// ================= K_scan: single-pass scan with aggregate lookback =========
__global__ void __launch_bounds__(256)
scan_kernel(int E)
{
    __shared__ int s_w[8];
    __shared__ int s_off;
    const int t = threadIdx.x, w = t >> 5, lane = t & 31;
    const int blk = blockIdx.x;
    const int i = blk * 256 + t;

    const int x = g_hist[i];
    int v = x;
    #pragma unroll
    for (int o = 1; o < 32; o <<= 1) {
        int y = __shfl_up_sync(0xFFFFFFFF, v, o);
        if (lane >= o) v += y;
    }
    if (lane == 31) s_w[w] = v;
    __syncthreads();
    if (t < 8) {
        int sv = s_w[t];
        #pragma unroll
        for (int o = 1; o < 8; o <<= 1) {
            int y = __shfl_up_sync(0xFF, sv, o);
            if (t >= o) sv += y;
        }
        s_w[t] = sv;
    }
    __syncthreads();
    const int local_excl = ((w > 0) ? s_w[w - 1] : 0) + v - x;

    if (t == 0) {
        int total = s_w[7];
        asm volatile("st.global.release.gpu.b32 [%0], %1;"
                     :: "l"(&g_hist[N_MAX + blk]), "r"(total + 1) : "memory");
    }
    if (w == 0) {
        int sum = 0;
        for (int j0 = 0; j0 < blk; j0 += 32) {
            const int j = j0 + lane;
            int a = 0;
            if (j < blk) {
                do {
                    asm volatile("ld.global.acquire.gpu.b32 %0, [%1];"
                                 : "=r"(a) : "l"(&g_hist[N_MAX + j]) : "memory");
                } while (a == 0);
                a -= 1;
            }
            #pragma unroll
            for (int o = 16; o > 0; o >>= 1) a += __shfl_down_sync(0xFFFFFFFF, a, o);
            if (lane == 0) sum += a;
        }
        if (lane == 0) s_off = sum;
    }
    __syncthreads();

    const int r = s_off + local_excl;
    g_rowptr[i] = r;
    g_cursor[i] = r;
    if (i == N_MAX - 1) g_rowptr[N_MAX] = E;
}

// ================= perm: scatter edges into src-sorted order ================
__global__ void __launch_bounds__(256)
perm_kernel(const int* __restrict__ esrc, const int* __restrict__ edst,
            const int* __restrict__ erel, const float* __restrict__ eval,
            const float* __restrict__ w_rel, int E)
{
    const int e = blockIdx.x * 256 + threadIdx.x;
    if (e >= E) return;
    const int s = esrc[e];
    const int pos = atomicAdd(&g_cursor[s], 1);
    g_dst_s[pos] = edst[e];
    const int r = erel[e];
    const float v = eval[e];
    float4 c;
    c.x = v * __ldg(w_rel + r * NBASES + 0);
    c.y = v * __ldg(w_rel + r * NBASES + 1);
    c.z = v * __ldg(w_rel + r * NBASES + 2);
    c.w = v * __ldg(w_rel + r * NBASES + 3);
    g_c_s[pos] = c;
}

// ================= GEMM: fp16 single-pass mma.sync =========================
#define AS_STRIDE 272
#define SM_A    0
#define SM_B    34816
#define SM_TOTAL 69632

__global__ void __launch_bounds__(256, 2)
gemm_mma_kernel(int n_rows)
{
    extern __shared__ char smem[];
    const uint32_t sb = smem_u32(smem);
    const int tid = threadIdx.x, wid = tid >> 5, lane = tid & 31;
    const int base = blockIdx.x;
    const int m0 = blockIdx.y * 128;

    for (int i = tid; i < 2048; i += 256) {
        const int row = i >> 4, seg = (i & 15) * 16;
        const size_t gsrc = (size_t)(m0 + row) * 256 + seg;
        uint4 hv = *reinterpret_cast<const uint4*>(reinterpret_cast<const char*>(g_Xh) + gsrc);
        *reinterpret_cast<uint4*>(smem + SM_A + row * AS_STRIDE + seg) = hv;
    }
    {
        const uint4* src = reinterpret_cast<const uint4*>(g_Bt[base]);
        uint4* dst = reinterpret_cast<uint4*>(smem + SM_B);
        for (int i = tid; i < 2176; i += 256) dst[i] = src[i];
    }
    __syncthreads();

    const int warp_m = (wid & 3) * 32;
    const int warp_n = (wid >> 2) * 64;

    float acc[2][8][4];
    #pragma unroll
    for (int mt = 0; mt < 2; ++mt)
        #pragma unroll
        for (int nt = 0; nt < 8; ++nt)
            #pragma unroll
            for (int i = 0; i < 4; ++i) acc[mt][nt][i] = 0.f;

    const uint32_t a_off = (uint32_t)(warp_m + (lane & 15)) * AS_STRIDE + (lane >> 4) * 16;
    const uint32_t b_off = (uint32_t)(warp_n + ((lane >> 4) << 3) + (lane & 7)) * AS_STRIDE
                         + ((lane >> 3) & 1) * 16;

    #pragma unroll
    for (int ks = 0; ks < 8; ++ks) {
        const uint32_t kb = (uint32_t)ks * 32;
        uint32_t ah[2][4];
        #pragma unroll
        for (int mt = 0; mt < 2; ++mt)
            LDSM4(ah[mt], sb + SM_A + a_off + (uint32_t)mt * 16 * AS_STRIDE + kb);
        #pragma unroll
        for (int j = 0; j < 4; ++j) {
            uint32_t b[4];
            LDSM4(b, sb + SM_B + b_off + (uint32_t)j * 16 * AS_STRIDE + kb);
            #pragma unroll
            for (int mt = 0; mt < 2; ++mt) {
                MMA_F16(acc[mt][2 * j + 0], ah[mt], b[0], b[1]);
                MMA_F16(acc[mt][2 * j + 1], ah[mt], b[2], b[3]);
            }
        }
    }

    const int r_base = m0 + warp_m + (lane >> 2);
    #pragma unroll
    for (int mt = 0; mt < 2; ++mt) {
        const int row0 = r_base + mt * 16;
        #pragma unroll
        for (int nt = 0; nt < 8; ++nt) {
            const int col = base * 128 + warp_n + nt * 8 + (lane & 3) * 2;
            *reinterpret_cast<__half2*>(g_XWh + (size_t)row0 * NCOLS + col) =
                __floats2half2_rn(acc[mt][nt][0], acc[mt][nt][1]);
            *reinterpret_cast<__half2*>(g_XWh + (size_t)(row0 + 8) * NCOLS + col) =
                __floats2half2_rn(acc[mt][nt][2], acc[mt][nt][3]);
        }
    }
}

// ================= scatter: warp-per-src, 2-deep pipelined edge loop ========
__global__ void __launch_bounds__(256)
scatter_kernel(float* __restrict__ out)
{
    const int src  = (blockIdx.x * 256 + threadIdx.x) >> 5;
    const int lane = threadIdx.x & 31;
    if (src >= N_MAX) return;
    const int beg = __ldg(g_rowptr + src);
    const int end = __ldg(g_rowptr + src + 1);
    if (beg >= end) return;

    const uint2* p = reinterpret_cast<const uint2*>(g_XWh + (size_t)src * NCOLS) + lane;
    float a[NBASES][4];
    #pragma unroll
    for (int b = 0; b < NBASES; ++b) {
        const uint2 v = __ldg(p + b * 32);
        const float2 lo = __half22float2(*reinterpret_cast<const __half2*>(&v.x));
        const float2 hi = __half22float2(*reinterpret_cast<const __half2*>(&v.y));
        a[b][0] = lo.x; a[b][1] = lo.y; a[b][2] = hi.x; a[b][3] = hi.y;
    }

    // software pipeline: prefetch edge j+1 while computing edge j
    float4 c = __ldg(g_c_s + beg);
    int    d = __ldg(g_dst_s + beg);
    for (int j = beg; j < end; ++j) {
        // unconditional prefetch (arrays sized E_MAX > E; j+1 <= end < E_MAX)
        const float4 cn = __ldg(g_c_s + j + 1);
        const int    dn = __ldg(g_dst_s + j + 1);
        float4 acc;
        acc.x = fmaf(c.x, a[0][0], fmaf(c.y, a[1][0], fmaf(c.z, a[2][0], c.w * a[3][0])));
        acc.y = fmaf(c.x, a[0][1], fmaf(c.y, a[1][1], fmaf(c.z, a[2][1], c.w * a[3][1])));
        acc.z = fmaf(c.x, a[0][2], fmaf(c.y, a[1][2], fmaf(c.z, a[2][2], c.w * a[3][2])));
        acc.w = fmaf(c.x, a[0][3], fmaf(c.y, a[1][3], fmaf(c.z, a[2][3], c.w * a[3][3])));
        float* q = out + (size_t)d * D_OUT + lane * 4;
        asm volatile("red.global.add.v4.f32 [%0], {%1, %2, %3, %4};"
                     :: "l"(q), "f"(acc.x), "f"(acc.y), "f"(acc.z), "f"(acc.w)
                     : "memory");
        c = cn;
        d = dn;
    }
}

// ================= launch =================
extern "C" void kernel_launch(void* const* d_in, const int* in_sizes, int n_in,
                              void* d_out, int out_size)
{
    const float* X       = (const float*)d_in[0];
    const int*   esrc    = (const int*)  d_in[1];
    const int*   edst    = (const int*)  d_in[2];
    const int*   erel    = (const int*)  d_in[3];
    const float* eval    = (const float*)d_in[4];
    const float* w_bases = (const float*)d_in[5];
    const float* w_rel   = (const float*)d_in[6];
    float*       out     = (float*)d_out;

    const int n = in_sizes[0] / D_IN;   // 100000
    const int E = in_sizes[1];          // 640000

    cudaFuncSetAttribute(gemm_mma_kernel, cudaFuncAttributeMaxDynamicSharedMemorySize, SM_TOTAL);

    void* hist_ptr = nullptr;
    cudaGetSymbolAddress(&hist_ptr, g_hist);
    cudaMemsetAsync(hist_ptr, 0, (size_t)(N_MAX + NBLK) * sizeof(int));

    const int total4 = n * D_IN / 4;
    const int out4 = out_size / 4;
    k1_kernel<<<4 * K1_RBLKS, 256>>>(X, w_bases, esrc, (float4*)d_out, total4, out4, E);
    scan_kernel<<<NBLK, 256>>>(E);
    perm_kernel<<<(E + 255) / 256, 256>>>(esrc, edst, erel, eval, w_rel, E);

    dim3 g1(NBASES, (n + 127) / 128);
    gemm_mma_kernel<<<g1, 256, SM_TOTAL>>>(n);

    scatter_kernel<<<N_MAX / 8, 256>>>(out);
}

// round 13
// speedup vs baseline: 1.0959x; 1.0655x over previous
#include <cuda_runtime.h>
#include <cuda_fp16.h>
#include <cstdint>

#define D_IN   128
#define D_OUT  128
#define NBASES 4
#define NCOLS  512
#define N_MAX  100096          // multiple of 256
#define NBLK   (N_MAX / 256)   // 391
#define E_MAX  655360
#define K1_RBLKS 296

// ---------------- scratch ----------------
__device__ __align__(16) __half g_XWh[(size_t)N_MAX * NCOLS];  // [node][512] fp16
__device__ __align__(16) __half g_Xh[(size_t)N_MAX * D_IN];    // fp16 X
#define BT_STRIDE 136
__device__ __align__(16) __half g_Bt[NBASES][128 * BT_STRIDE];
// hist[N_MAX] | scan aggregates[NBLK]  (zeroed by one memset)
__device__ int    g_hist[N_MAX + NBLK];
__device__ int    g_rowptr[N_MAX + 1];
__device__ int    g_cursor[N_MAX];
__device__ int    g_dst_s[E_MAX];
__device__ float4 g_c_s[E_MAX];

// ---------------- helpers ----------------
static __device__ __forceinline__ uint32_t smem_u32(const void* p) {
    uint32_t a;
    asm("{ .reg .u64 t; cvta.to.shared.u64 t, %1; cvt.u32.u64 %0, t; }" : "=r"(a) : "l"(p));
    return a;
}
#define LDSM4(r, addr) \
    asm volatile("ldmatrix.sync.aligned.m8n8.x4.shared.b16 {%0,%1,%2,%3}, [%4];" \
        : "=r"((r)[0]), "=r"((r)[1]), "=r"((r)[2]), "=r"((r)[3]) : "r"(addr))
#define MMA_F16(c, a, b0, b1) \
    asm volatile("mma.sync.aligned.m16n8k16.row.col.f32.f16.f16.f32 " \
        "{%0,%1,%2,%3}, {%4,%5,%6,%7}, {%8,%9}, {%0,%1,%2,%3};" \
        : "+f"((c)[0]), "+f"((c)[1]), "+f"((c)[2]), "+f"((c)[3]) \
        : "r"((a)[0]), "r"((a)[1]), "r"((a)[2]), "r"((a)[3]), "r"(b0), "r"(b1))

static __device__ __forceinline__ uint32_t packh(__half a, __half b) {
    return ((uint32_t)__half_as_ushort(b) << 16) | (uint32_t)__half_as_ushort(a);
}

// ================= K1: zero-out | convert_x | hist | prep_b =================
__global__ void __launch_bounds__(256)
k1_kernel(const float* __restrict__ X,
          const float* __restrict__ w_bases,
          const int*   __restrict__ esrc,
          float4*      __restrict__ out,
          int total4, int out4, int E)
{
    const int region = blockIdx.x / K1_RBLKS;          // 0..3
    const int tid0 = (blockIdx.x % K1_RBLKS) * 256 + threadIdx.x;
    const int stride = K1_RBLKS * 256;

    if (region == 0) {
        const float4 z = make_float4(0.f, 0.f, 0.f, 0.f);
        for (int i = tid0; i < out4; i += stride) out[i] = z;
    } else if (region == 1) {
        for (int i = tid0; i < total4; i += stride) {
            float4 v = reinterpret_cast<const float4*>(X)[i];
            reinterpret_cast<uint2*>(g_Xh)[i] =
                make_uint2(packh(__float2half_rn(v.x), __float2half_rn(v.y)),
                           packh(__float2half_rn(v.z), __float2half_rn(v.w)));
        }
    } else if (region == 2) {
        for (int e = tid0; e < E; e += stride) atomicAdd(&g_hist[esrc[e]], 1);
    } else {
        for (int id = tid0; id < NBASES * D_IN * D_OUT; id += stride) {
            const int nn = id & 127, k = (id >> 7) & 127, b = id >> 14;
            g_Bt[b][nn * BT_STRIDE + k] = __float2half_rn(w_bases[id]);
        }
    }
}

// ================= K_scan: single-pass scan with aggregate lookback =========
__global__ void __launch_bounds__(256)
scan_kernel(int E)
{
    __shared__ int s_w[8];
    __shared__ int s_off;
    const int t = threadIdx.x, w = t >> 5, lane = t & 31;
    const int blk = blockIdx.x;
    const int i = blk * 256 + t;

    const int x = g_hist[i];
    int v = x;
    #pragma unroll
    for (int o = 1; o < 32; o <<= 1) {
        int y = __shfl_up_sync(0xFFFFFFFF, v, o);
        if (lane >= o) v += y;
    }
    if (lane == 31) s_w[w] = v;
    __syncthreads();
    if (t < 8) {
        int sv = s_w[t];
        #pragma unroll
        for (int o = 1; o < 8; o <<= 1) {
            int y = __shfl_up_sync(0xFF, sv, o);
            if (t >= o) sv += y;
        }
        s_w[t] = sv;
    }
    __syncthreads();
    const int local_excl = ((w > 0) ? s_w[w - 1] : 0) + v - x;

    if (t == 0) {
        int total = s_w[7];
        asm volatile("st.global.release.gpu.b32 [%0], %1;"
                     :: "l"(&g_hist[N_MAX + blk]), "r"(total + 1) : "memory");
    }
    if (w == 0) {
        int sum = 0;
        for (int j0 = 0; j0 < blk; j0 += 32) {
            const int j = j0 + lane;
            int a = 0;
            if (j < blk) {
                do {
                    asm volatile("ld.global.acquire.gpu.b32 %0, [%1];"
                                 : "=r"(a) : "l"(&g_hist[N_MAX + j]) : "memory");
                } while (a == 0);
                a -= 1;
            }
            #pragma unroll
            for (int o = 16; o > 0; o >>= 1) a += __shfl_down_sync(0xFFFFFFFF, a, o);
            if (lane == 0) sum += a;
        }
        if (lane == 0) s_off = sum;
    }
    __syncthreads();

    const int r = s_off + local_excl;
    g_rowptr[i] = r;
    g_cursor[i] = r;
    if (i == N_MAX - 1) g_rowptr[N_MAX] = E;
}

// ================= perm: scatter edges into src-sorted order ================
__global__ void __launch_bounds__(256)
perm_kernel(const int* __restrict__ esrc, const int* __restrict__ edst,
            const int* __restrict__ erel, const float* __restrict__ eval,
            const float* __restrict__ w_rel, int E)
{
    const int e = blockIdx.x * 256 + threadIdx.x;
    if (e >= E) return;
    const int s = esrc[e];
    const int pos = atomicAdd(&g_cursor[s], 1);
    g_dst_s[pos] = edst[e];
    const int r = erel[e];
    const float v = eval[e];
    float4 c;
    c.x = v * __ldg(w_rel + r * NBASES + 0);
    c.y = v * __ldg(w_rel + r * NBASES + 1);
    c.z = v * __ldg(w_rel + r * NBASES + 2);
    c.w = v * __ldg(w_rel + r * NBASES + 3);
    g_c_s[pos] = c;
}

// ====== GEMM: fp16 mma.sync, 128x64 tiles, 4 CTAs/SM (occupancy fix) =======
#define AS_STRIDE 272
#define SM_A    0
#define SM_B    34816                      // A = 128 rows * 272B
#define SM_TOTAL (34816 + 17408)           // + B = 64 rows * 272B -> 52224

__global__ void __launch_bounds__(256, 4)
gemm_mma_kernel(int n_rows)
{
    extern __shared__ char smem[];
    const uint32_t sb = smem_u32(smem);
    const int tid = threadIdx.x, wid = tid >> 5, lane = tid & 31;
    const int nc = blockIdx.x;             // n-chunk 0..7 (fastest -> A L2 reuse)
    const int base = nc >> 1, half = nc & 1;
    const int m0 = blockIdx.y * 128;

    // A: 128 rows x 256B into 272B-stride rows
    for (int i = tid; i < 2048; i += 256) {
        const int row = i >> 4, seg = (i & 15) * 16;
        const size_t gsrc = (size_t)(m0 + row) * 256 + seg;
        uint4 hv = *reinterpret_cast<const uint4*>(reinterpret_cast<const char*>(g_Xh) + gsrc);
        *reinterpret_cast<uint4*>(smem + SM_A + row * AS_STRIDE + seg) = hv;
    }
    // B: 64 rows (output cols) x 272B, linear copy from pre-built image
    {
        const uint4* src = reinterpret_cast<const uint4*>(g_Bt[base] + half * 64 * BT_STRIDE);
        uint4* dst = reinterpret_cast<uint4*>(smem + SM_B);
        for (int i = tid; i < 1088; i += 256) dst[i] = src[i];
    }
    __syncthreads();

    const int warp_m = (wid & 3) * 32;     // 4 warps in m
    const int warp_n = (wid >> 2) * 32;    // 2 warps in n (of 64 cols)

    float acc[2][4][4];
    #pragma unroll
    for (int mt = 0; mt < 2; ++mt)
        #pragma unroll
        for (int nt = 0; nt < 4; ++nt)
            #pragma unroll
            for (int i = 0; i < 4; ++i) acc[mt][nt][i] = 0.f;

    const uint32_t a_off = (uint32_t)(warp_m + (lane & 15)) * AS_STRIDE + (lane >> 4) * 16;
    const uint32_t b_off = (uint32_t)(warp_n + ((lane >> 4) << 3) + (lane & 7)) * AS_STRIDE
                         + ((lane >> 3) & 1) * 16;

    #pragma unroll
    for (int ks = 0; ks < 8; ++ks) {
        const uint32_t kb = (uint32_t)ks * 32;
        uint32_t ah[2][4];
        LDSM4(ah[0], sb + SM_A + a_off + kb);
        LDSM4(ah[1], sb + SM_A + a_off + 16 * AS_STRIDE + kb);
        #pragma unroll
        for (int j = 0; j < 2; ++j) {
            uint32_t b[4];
            LDSM4(b, sb + SM_B + b_off + (uint32_t)j * 16 * AS_STRIDE + kb);
            #pragma unroll
            for (int mt = 0; mt < 2; ++mt) {
                MMA_F16(acc[mt][2 * j + 0], ah[mt], b[0], b[1]);
                MMA_F16(acc[mt][2 * j + 1], ah[mt], b[2], b[3]);
            }
        }
    }

    const int r_base = m0 + warp_m + (lane >> 2);
    #pragma unroll
    for (int mt = 0; mt < 2; ++mt) {
        const int row0 = r_base + mt * 16;
        #pragma unroll
        for (int nt = 0; nt < 4; ++nt) {
            const int col = nc * 64 + warp_n + nt * 8 + (lane & 3) * 2;
            *reinterpret_cast<__half2*>(g_XWh + (size_t)row0 * NCOLS + col) =
                __floats2half2_rn(acc[mt][nt][0], acc[mt][nt][1]);
            *reinterpret_cast<__half2*>(g_XWh + (size_t)(row0 + 8) * NCOLS + col) =
                __floats2half2_rn(acc[mt][nt][2], acc[mt][nt][3]);
        }
    }
}

// ================= scatter: warp-per-src (round-7 proven form) ==============
__global__ void __launch_bounds__(256)
scatter_kernel(float* __restrict__ out)
{
    const int src  = (blockIdx.x * 256 + threadIdx.x) >> 5;
    const int lane = threadIdx.x & 31;
    if (src >= N_MAX) return;
    const int beg = __ldg(g_rowptr + src);
    const int end = __ldg(g_rowptr + src + 1);
    if (beg >= end) return;

    const uint2* p = reinterpret_cast<const uint2*>(g_XWh + (size_t)src * NCOLS) + lane;
    float a[NBASES][4];
    #pragma unroll
    for (int b = 0; b < NBASES; ++b) {
        const uint2 v = __ldg(p + b * 32);
        const float2 lo = __half22float2(*reinterpret_cast<const __half2*>(&v.x));
        const float2 hi = __half22float2(*reinterpret_cast<const __half2*>(&v.y));
        a[b][0] = lo.x; a[b][1] = lo.y; a[b][2] = hi.x; a[b][3] = hi.y;
    }

    for (int j = beg; j < end; ++j) {
        const float4 c = __ldg(g_c_s + j);
        const int d = __ldg(g_dst_s + j);
        float4 acc;
        acc.x = fmaf(c.x, a[0][0], fmaf(c.y, a[1][0], fmaf(c.z, a[2][0], c.w * a[3][0])));
        acc.y = fmaf(c.x, a[0][1], fmaf(c.y, a[1][1], fmaf(c.z, a[2][1], c.w * a[3][1])));
        acc.z = fmaf(c.x, a[0][2], fmaf(c.y, a[1][2], fmaf(c.z, a[2][2], c.w * a[3][2])));
        acc.w = fmaf(c.x, a[0][3], fmaf(c.y, a[1][3], fmaf(c.z, a[2][3], c.w * a[3][3])));
        float* q = out + (size_t)d * D_OUT + lane * 4;
        asm volatile("red.global.add.v4.f32 [%0], {%1, %2, %3, %4};"
                     :: "l"(q), "f"(acc.x), "f"(acc.y), "f"(acc.z), "f"(acc.w)
                     : "memory");
    }
}

// ================= launch =================
extern "C" void kernel_launch(void* const* d_in, const int* in_sizes, int n_in,
                              void* d_out, int out_size)
{
    const float* X       = (const float*)d_in[0];
    const int*   esrc    = (const int*)  d_in[1];
    const int*   edst    = (const int*)  d_in[2];
    const int*   erel    = (const int*)  d_in[3];
    const float* eval    = (const float*)d_in[4];
    const float* w_bases = (const float*)d_in[5];
    const float* w_rel   = (const float*)d_in[6];
    float*       out     = (float*)d_out;

    const int n = in_sizes[0] / D_IN;   // 100000
    const int E = in_sizes[1];          // 640000

    cudaFuncSetAttribute(gemm_mma_kernel, cudaFuncAttributeMaxDynamicSharedMemorySize, SM_TOTAL);

    void* hist_ptr = nullptr;
    cudaGetSymbolAddress(&hist_ptr, g_hist);
    cudaMemsetAsync(hist_ptr, 0, (size_t)(N_MAX + NBLK) * sizeof(int));

    const int total4 = n * D_IN / 4;
    const int out4 = out_size / 4;
    k1_kernel<<<4 * K1_RBLKS, 256>>>(X, w_bases, esrc, (float4*)d_out, total4, out4, E);
    scan_kernel<<<NBLK, 256>>>(E);
    perm_kernel<<<(E + 255) / 256, 256>>>(esrc, edst, erel, eval, w_rel, E);

    dim3 g1(8, (n + 127) / 128);
    gemm_mma_kernel<<<g1, 256, SM_TOTAL>>>(n);

    scatter_kernel<<<N_MAX / 8, 256>>>(out);
}